// round 1
// baseline (speedup 1.0000x reference)
#include <cuda_runtime.h>
#include <cuda_bf16.h>

// Problem constants (fixed by setup_inputs)
#define BB 2
#define LL 2048
#define SSS 2048
#define HH 8
#define EE 64

#define BT 64      // L/S tile
#define PAD 68     // smem row stride (floats); 272B rows keep float4 alignment
#define NTHREADS 256

#define MASK_SCALE 10000.0f
#define NEG_BIG (-1e30f)

__global__ __launch_bounds__(NTHREADS)
void phi_softmax_kernel(const float* __restrict__ q,
                        const float* __restrict__ kk,
                        const float* __restrict__ vv_,
                        const int*   __restrict__ pos,
                        const int*   __restrict__ causal_flag,
                        const int*   __restrict__ hard,
                        const float* __restrict__ phi,
                        const float* __restrict__ log_tau,
                        const float* __restrict__ threshold,
                        const float* __restrict__ uu_,
                        float*       __restrict__ out)
{
    extern __shared__ float smem[];
    float (*Qs)[PAD] = (float(*)[PAD])(smem);
    float (*Ks)[PAD] = (float(*)[PAD])(smem + BT * PAD);
    float (*Vs)[PAD] = (float(*)[PAD])(smem + 2 * BT * PAD);
    float (*Ps)[PAD] = (float(*)[PAD])(smem + 3 * BT * PAD);
    int* posl = (int*)(smem + 4 * BT * PAD);
    int* poss = posl + BT;

    const int b  = blockIdx.x;                       // batch fastest -> phi/u L2 reuse across b
    const int h  = blockIdx.y;
    const int lt = gridDim.z - 1 - blockIdx.z;       // heavy (large-l) tiles first
    const int l0 = lt * BT;

    const int tid = threadIdx.x;
    const int tx  = tid & 15;    // column group (s / e)
    const int ty  = tid >> 4;    // row group (l)

    const float scale = 0.125f;  // 1/sqrt(64)
    float tau = __expf(log_tau[0]);
    tau = fminf(fmaxf(tau, 0.1f), 5.0f);
    const float inv_tau = 1.0f / tau;
    float thr = threshold[0];
    thr = fminf(fmaxf(thr, 0.01f), 0.99f);
    const int causal = causal_flag[0];

    // ---- load Q tile (rows l0..l0+63, all 64 e) ----
    #pragma unroll
    for (int i = tid; i < BT * (EE / 4); i += NTHREADS) {
        int r  = i >> 4;
        int ec = (i & 15) * 4;
        *(float4*)&Qs[r][ec] =
            *(const float4*)&q[((b * LL + l0 + r) * HH + h) * EE + ec];
    }
    if (tid < BT) posl[tid] = pos[b * LL + l0 + tid];

    // accumulators
    float acc[4][4];
    float mrun[4], lrun[4];
    #pragma unroll
    for (int i = 0; i < 4; i++) {
        mrun[i] = NEG_BIG; lrun[i] = 0.0f;
        #pragma unroll
        for (int j = 0; j < 4; j++) acc[i][j] = 0.0f;
    }

    const int nst = causal ? (lt + 1) : (SSS / BT);

    for (int st = 0; st < nst; st++) {
        const int s0 = st * BT;
        __syncthreads();   // prior-iter GEMM2 reads (Ks/Vs/Ps) done; Q visible on iter 0

        // ---- load K and V tiles ----
        #pragma unroll
        for (int i = tid; i < BT * (EE / 4); i += NTHREADS) {
            int r  = i >> 4;
            int ec = (i & 15) * 4;
            int base = ((b * SSS + s0 + r) * HH + h) * EE + ec;
            *(float4*)&Ks[r][ec] = *(const float4*)&kk[base];
            *(float4*)&Vs[r][ec] = *(const float4*)&vv_[base];
        }
        if (tid < BT) poss[tid] = pos[b * LL + s0 + tid];
        __syncthreads();

        // ---- GEMM1: cc[i][j] = Q[ty+16i] . K[tx+16j] ----
        float cc[4][4];
        #pragma unroll
        for (int i = 0; i < 4; i++)
            #pragma unroll
            for (int j = 0; j < 4; j++) cc[i][j] = 0.0f;

        #pragma unroll
        for (int e = 0; e < EE; e += 4) {
            float4 qv[4], kv[4];
            #pragma unroll
            for (int i = 0; i < 4; i++) qv[i] = *(const float4*)&Qs[ty + 16 * i][e];
            #pragma unroll
            for (int j = 0; j < 4; j++) kv[j] = *(const float4*)&Ks[tx + 16 * j][e];
            #pragma unroll
            for (int i = 0; i < 4; i++)
                #pragma unroll
                for (int j = 0; j < 4; j++)
                    cc[i][j] += qv[i].x * kv[j].x + qv[i].y * kv[j].y
                              + qv[i].z * kv[j].z + qv[i].w * kv[j].w;
        }

        // ---- masks + dag penalty + online softmax ----
        #pragma unroll
        for (int i = 0; i < 4; i++) {
            const int rl = ty + 16 * i;
            const int lg = l0 + rl;
            const int pl = posl[rl];
            float rowmax = NEG_BIG;
            #pragma unroll
            for (int j = 0; j < 4; j++) {
                const int cs = tx + 16 * j;
                const int sg = s0 + cs;
                const int idx = (h * LL + lg) * SSS + sg;
                const float ph = __ldg(&phi[idx]);
                const float uv = __ldg(&uu_[idx]);
                const int   hm = __ldg(&hard[lg * SSS + sg]);
                const float g  = __logf(uv + 1e-8f) - __logf(1.0f - uv + 1e-8f);
                const float z  = (g + ph) * inv_tau;
                const float sg_ = 1.0f / (1.0f + __expf(-z));
                const float dag = MASK_SCALE * fminf(sg_ - thr, 0.0f);
                float logit = scale * (cc[i][j] + dag);
                const bool masked = (hm == 0) || (causal && (poss[cs] > pl));
                logit = masked ? NEG_BIG : logit;
                cc[i][j] = logit;
                rowmax = fmaxf(rowmax, logit);
            }
            #pragma unroll
            for (int o = 8; o > 0; o >>= 1)
                rowmax = fmaxf(rowmax, __shfl_xor_sync(0xffffffffu, rowmax, o, 16));

            const float mnew = fmaxf(mrun[i], rowmax);
            float alpha, lsum = 0.0f;
            if (mnew <= -1e29f) {      // row fully masked so far
                alpha = 1.0f;
                #pragma unroll
                for (int j = 0; j < 4; j++) Ps[rl][tx + 16 * j] = 0.0f;
            } else {
                alpha = __expf(mrun[i] - mnew);
                #pragma unroll
                for (int j = 0; j < 4; j++) {
                    float p = __expf(cc[i][j] - mnew);   // masked -> exp(-huge) = 0
                    lsum += p;
                    Ps[rl][tx + 16 * j] = p;
                }
            }
            mrun[i] = mnew;
            lrun[i] = lrun[i] * alpha + lsum;
            #pragma unroll
            for (int j = 0; j < 4; j++) acc[i][j] *= alpha;
        }
        __syncthreads();

        // ---- GEMM2: acc[i][j] += P[ty+16i][s] * V[s][tx+16j] ----
        #pragma unroll 4
        for (int s = 0; s < BT; s++) {
            float pv[4], vvv[4];
            #pragma unroll
            for (int i = 0; i < 4; i++) pv[i] = Ps[ty + 16 * i][s];
            #pragma unroll
            for (int j = 0; j < 4; j++) vvv[j] = Vs[s][tx + 16 * j];
            #pragma unroll
            for (int i = 0; i < 4; i++)
                #pragma unroll
                for (int j = 0; j < 4; j++) acc[i][j] += pv[i] * vvv[j];
        }
    }

    // ---- finalize: reduce row sums across the 16 column threads, write out ----
    #pragma unroll
    for (int i = 0; i < 4; i++) {
        float ls = lrun[i];
        #pragma unroll
        for (int o = 8; o > 0; o >>= 1)
            ls += __shfl_xor_sync(0xffffffffu, ls, o, 16);
        const float inv = 1.0f / ls;   // diagonal is always open -> ls >= ~1
        const int lg = l0 + ty + 16 * i;
        const int obase = ((b * LL + lg) * HH + h) * EE;
        #pragma unroll
        for (int j = 0; j < 4; j++)
            out[obase + tx + 16 * j] = acc[i][j] * inv;
    }
}

extern "C" void kernel_launch(void* const* d_in, const int* in_sizes, int n_in,
                              void* d_out, int out_size)
{
    const float* q        = (const float*)d_in[0];
    const float* k        = (const float*)d_in[1];
    const float* v        = (const float*)d_in[2];
    // d_in[3] mask_miss_k, d_in[4] mask_miss_q: unused in forward
    const int*   pos      = (const int*)d_in[5];
    const int*   causal   = (const int*)d_in[6];
    const int*   hard     = (const int*)d_in[7];
    const float* phi      = (const float*)d_in[8];
    const float* log_tau  = (const float*)d_in[9];
    const float* thr      = (const float*)d_in[10];
    const float* u        = (const float*)d_in[11];
    float* out            = (float*)d_out;

    const int smem_bytes = (4 * BT * PAD) * sizeof(float) + 2 * BT * sizeof(int);
    cudaFuncSetAttribute(phi_softmax_kernel,
                         cudaFuncAttributeMaxDynamicSharedMemorySize, smem_bytes);

    dim3 grid(BB, HH, LL / BT);   // b fastest -> batches share phi/u via L2
    phi_softmax_kernel<<<grid, NTHREADS, smem_bytes>>>(
        q, k, v, pos, causal, hard, phi, log_tau, thr, u, out);
}